// round 1
// baseline (speedup 1.0000x reference)
#include <cuda_runtime.h>
#include <cstdint>

#define D    100
#define DP1  101
#define Kn   32
#define NBA  4            // nodes per block, kernel A
#define RWS  (NBA*Kn)     // 128 rows
#define RP   132          // padded row stride for tT (float4-aligned, low bank conflict)
#define CP   104          // padded col count (multiple of 8)
#define TA   256          // threads kernel A
#define NBB  16           // nodes per block, kernel B
#define NMAX 50000

__device__ float g_msg[NMAX * D];   // scratch: attention message per node

// ---------------------------------------------------------------------------
// Kernel A: attention message. One block = NBA nodes.
//  tT[d][row] = emb[nei[row]][d] * s_vec[node][d]  (row = node*32+k), tT[100][row]=wei
//  z[row][j]  = bias[j] + sum_d tT[d][row] * W1[d][j]        (128x104 GEMM, 8x8 tiles)
//  score[row] = sum_j q1[j] * tanh(z[row][j])
//  att = softmax_k(score);  msg[node][d] = (sum_k att*tT[d][row]) / s[node][d]
// ---------------------------------------------------------------------------
__global__ void __launch_bounds__(TA, 2)
attn_kernel(const int* __restrict__ nei, const float* __restrict__ wei,
            const float* __restrict__ s_vec, const float* __restrict__ emb,
            const float* __restrict__ W1w, const float* __restrict__ W1b,
            const float* __restrict__ q1w, int Ntot)
{
    extern __shared__ float sm[];
    float* tT    = sm;                    // [DP1][RP]  13332 f
    float* W1s   = tT + DP1 * RP;         // [DP1][CP]  10504 f
    float* bsh   = W1s + DP1 * CP;        // [CP]
    float* q1s   = bsh + CP;              // [CP]
    float* ss    = q1s + CP;              // [NBA][D]
    float* score = ss + NBA * D;          // [RWS] (scores, then att)
    int*   nbid  = (int*)(score + RWS);   // [RWS]

    const int tid   = threadIdx.x;
    const int node0 = blockIdx.x * NBA;
    if (node0 >= Ntot) return;

    // ---- stage weights / per-node data ----
    for (int i = tid; i < DP1 * CP; i += TA) {
        int d = i / CP, j = i - d * CP;
        W1s[i] = (j < D) ? W1w[d * D + j] : 0.f;
    }
    for (int j = tid; j < CP; j += TA) {
        bsh[j] = (j < D) ? W1b[j] : 0.f;
        q1s[j] = (j < D) ? q1w[j] : 0.f;
    }
    for (int i = tid; i < NBA * D; i += TA) ss[i] = s_vec[node0 * D + i];
    for (int r = tid; r < RWS; r += TA) {
        int node = r >> 5, k = r & 31;
        nbid[r] = nei[(node0 + node) * Kn + k];
        tT[100 * RP + r] = wei[(node0 + node) * Kn + k];
        score[r] = 0.f;
    }
    __syncthreads();

    // ---- gather neighbor embeddings, scale by s, store transposed ----
    for (int i = tid; i < RWS * D; i += TA) {
        int r = i / D, d = i - r * D;                 // consecutive d -> coalesced
        float h = emb[(size_t)nbid[r] * D + d];
        tT[d * RP + r] = h * ss[(r >> 5) * D + d];
    }
    __syncthreads();

    // ---- 128x104x101 GEMM, 8x8 register tiles (16 rowgroups x 13 colgroups) ----
    if (tid < 208) {
        const int rg = tid & 15, cg = tid >> 4;
        const int r0 = rg * 8, c0 = cg * 8;
        float acc[8][8];
        #pragma unroll
        for (int cc = 0; cc < 8; ++cc) {
            float b = bsh[c0 + cc];
            #pragma unroll
            for (int rr = 0; rr < 8; ++rr) acc[rr][cc] = b;
        }
        for (int d = 0; d < DP1; ++d) {
            const float* tp = &tT[d * RP + r0];
            float4 ta = *(const float4*)tp;
            float4 tb = *(const float4*)(tp + 4);
            const float* wp = &W1s[d * CP + c0];
            float4 wa = *(const float4*)wp;
            float4 wb = *(const float4*)(wp + 4);
            float tv[8] = {ta.x, ta.y, ta.z, ta.w, tb.x, tb.y, tb.z, tb.w};
            float wv[8] = {wa.x, wa.y, wa.z, wa.w, wb.x, wb.y, wb.z, wb.w};
            #pragma unroll
            for (int rr = 0; rr < 8; ++rr)
                #pragma unroll
                for (int cc = 0; cc < 8; ++cc)
                    acc[rr][cc] += tv[rr] * wv[cc];
        }
        // tanh + q1 dot, partial per rowgroup
        #pragma unroll
        for (int rr = 0; rr < 8; ++rr) {
            float p = 0.f;
            #pragma unroll
            for (int cc = 0; cc < 8; ++cc) {
                float z  = acc[rr][cc];
                float e  = __expf(2.f * z);
                float th = 1.f - __fdividef(2.f, e + 1.f);   // tanh(z)
                p += q1s[c0 + cc] * th;
            }
            atomicAdd(&score[r0 + rr], p);
        }
    }
    __syncthreads();

    // ---- softmax over K=32 per node (one warp per node) ----
    {
        const int w = tid >> 5, l = tid & 31;
        if (w < NBA) {
            float sc = score[w * 32 + l];
            float mx = sc;
            #pragma unroll
            for (int off = 16; off > 0; off >>= 1)
                mx = fmaxf(mx, __shfl_xor_sync(0xFFFFFFFFu, mx, off));
            float e = __expf(sc - mx);
            float sum = e;
            #pragma unroll
            for (int off = 16; off > 0; off >>= 1)
                sum += __shfl_xor_sync(0xFFFFFFFFu, sum, off);
            score[w * 32 + l] = e / sum;      // att
        }
    }
    __syncthreads();

    // ---- msg[node][d] = (sum_k att * t) / s  (t = h*s) ----
    for (int idx = tid; idx < NBA * D; idx += TA) {
        int node = idx / D, d = idx - node * D;
        const float* tr = &tT[d * RP + node * Kn];
        const float* at = &score[node * Kn];
        float a = 0.f;
        #pragma unroll
        for (int k = 0; k < Kn; ++k) a += at[k] * tr[k];
        float sv = ss[idx];
        float m;
        if (fabsf(sv) > 1e-30f) {
            m = a / sv;
        } else {                         // near-impossible fallback: re-gather h
            m = 0.f;
            for (int k = 0; k < Kn; ++k)
                m += at[k] * emb[(size_t)nbid[node * Kn + k] * D + d];
        }
        g_msg[(node0 + node) * D + d] = m;
    }
}

// ---------------------------------------------------------------------------
// Kernel B: x = emb[nodes]; twice: x = relu([x, msg] @ W2 + b2).
// One block = 16 nodes, blockDim (100, 4), W2 staged in smem once per block.
// ---------------------------------------------------------------------------
__global__ void __launch_bounds__(400, 2)
mlp_kernel(const int* __restrict__ nodes, const float* __restrict__ emb,
           const float* __restrict__ W2w, const float* __restrict__ W2b,
           float* __restrict__ out, int Ntot)
{
    extern __shared__ float sm[];
    float* W2s = sm;                 // [2D][D] 20000 f
    float* b2s = W2s + 2 * D * D;    // [D]
    float* xs  = b2s + D;            // [16][D]
    float* ms  = xs + NBB * D;       // [16][D]
    float* x1s = ms + NBB * D;       // [16][D]

    const int tx = threadIdx.x;           // j
    const int ty = threadIdx.y;
    const int tid = ty * D + tx;
    const int node0 = blockIdx.x * NBB;
    if (node0 >= Ntot) return;

    for (int i = tid; i < 2 * D * D; i += 400) W2s[i] = W2w[i];
    for (int i = tid; i < D; i += 400) b2s[i] = W2b[i];
    for (int i = tid; i < NBB * D; i += 400) {
        int n = i / D, d = i - n * D;
        xs[i] = emb[(size_t)nodes[node0 + n] * D + d];
        ms[i] = g_msg[node0 * D + i];
    }
    __syncthreads();

    const int j = tx;
    #pragma unroll
    for (int layer = 0; layer < 2; ++layer) {
        const float* INP = (layer == 0) ? xs : x1s;
        float acc[4];
        #pragma unroll
        for (int m = 0; m < 4; ++m) acc[m] = b2s[j];
        #pragma unroll 5
        for (int d4 = 0; d4 < D; d4 += 4) {
            float wA[4], wB[4];
            #pragma unroll
            for (int u = 0; u < 4; ++u) {
                wA[u] = W2s[(d4 + u) * D + j];
                wB[u] = W2s[(D + d4 + u) * D + j];
            }
            #pragma unroll
            for (int m = 0; m < 4; ++m) {
                int n = ty + 4 * m;
                float4 xv = *(const float4*)&INP[n * D + d4];
                float4 mv = *(const float4*)&ms[n * D + d4];
                acc[m] += xv.x * wA[0] + xv.y * wA[1] + xv.z * wA[2] + xv.w * wA[3]
                        + mv.x * wB[0] + mv.y * wB[1] + mv.z * wB[2] + mv.w * wB[3];
            }
        }
        if (layer == 0) {
            #pragma unroll
            for (int m = 0; m < 4; ++m)
                x1s[(ty + 4 * m) * D + j] = fmaxf(acc[m], 0.f);
            __syncthreads();
        } else {
            #pragma unroll
            for (int m = 0; m < 4; ++m)
                out[(size_t)(node0 + ty + 4 * m) * D + j] = fmaxf(acc[m], 0.f);
        }
    }
}

// ---------------------------------------------------------------------------
extern "C" void kernel_launch(void* const* d_in, const int* in_sizes, int n_in,
                              void* d_out, int out_size)
{
    const int*   nodes = (const int*)  d_in[0];
    const int*   nei   = (const int*)  d_in[1];
    const float* wei   = (const float*)d_in[2];
    const float* s_vec = (const float*)d_in[3];
    const float* emb   = (const float*)d_in[4];
    const float* W1w   = (const float*)d_in[5];
    const float* W1b   = (const float*)d_in[6];
    const float* q1w   = (const float*)d_in[7];
    const float* W2w   = (const float*)d_in[8];
    const float* W2b   = (const float*)d_in[9];
    float* out = (float*)d_out;

    const int N = in_sizes[0];

    const int smemA = (DP1 * RP + DP1 * CP + CP + CP + NBA * D + RWS) * 4 + RWS * 4;
    const int smemB = (2 * D * D + D + 3 * NBB * D) * 4;

    cudaFuncSetAttribute(attn_kernel, cudaFuncAttributeMaxDynamicSharedMemorySize, smemA);
    cudaFuncSetAttribute(mlp_kernel,  cudaFuncAttributeMaxDynamicSharedMemorySize, smemB);

    attn_kernel<<<(N + NBA - 1) / NBA, TA, smemA>>>(nei, wei, s_vec, emb, W1w, W1b, q1w, N);
    mlp_kernel<<<(N + NBB - 1) / NBB, dim3(D, 4), smemB>>>(nodes, emb, W2w, W2b, out, N);
}